// round 9
// baseline (speedup 1.0000x reference)
#include <cuda_runtime.h>
#include <cuda_bf16.h>
#include <math.h>
#include <stdint.h>

// Problem constants
#define BB 512
#define TT 1024
#define FF 128
#define UU 50
#define GG 200            // 4*U gate columns
#define NROWS (BB * TT)   // 524288 GEMM rows
#define MT32 (NROWS / 32) // 16384 m32 tiles
#define NCTA_P 288        // proj CTAs (2 per SM, 3 N-groups x 96)
#define WSTRIDE_P (96 * 8)// m32-tile warp stride per N-group

// Scratch: xproj[b*T + t][200] = x[b,t,:] @ kernel (fp32)
__device__ float g_xproj[(size_t)NROWS * GG];

// ---------------------------------------------------------------------------
// helpers
// ---------------------------------------------------------------------------
__device__ __forceinline__ uint32_t smem_u32(const void* p) {
    uint32_t a;
    asm("{ .reg .u64 t; cvta.to.shared.u64 t, %1; cvt.u32.u64 %0, t; }" : "=r"(a) : "l"(p));
    return a;
}

__device__ __forceinline__ uint32_t bf2pack(float a, float b) {
    __nv_bfloat162 t = __floats2bfloat162_rn(a, b);
    return *reinterpret_cast<uint32_t*>(&t);
}

// pack top 16 bits of two floats into bf16x2 (truncation split, 1 instr)
__device__ __forceinline__ uint32_t hipack(float a, float b) {
    uint32_t d;
    asm("prmt.b32 %0, %1, %2, 0x7632;" : "=r"(d)
        : "r"(__float_as_uint(a)), "r"(__float_as_uint(b)));
    return d;
}
__device__ __forceinline__ float trunc_hi(float v) {
    return __uint_as_float(__float_as_uint(v) & 0xffff0000u);
}

__device__ __forceinline__ void mma16816(float* d, uint32_t a0, uint32_t a1,
                                         uint32_t a2, uint32_t a3,
                                         uint32_t b0, uint32_t b1) {
    asm volatile(
        "mma.sync.aligned.m16n8k16.row.col.f32.bf16.bf16.f32 "
        "{%0,%1,%2,%3}, {%4,%5,%6,%7}, {%8,%9}, {%0,%1,%2,%3};"
        : "+f"(d[0]), "+f"(d[1]), "+f"(d[2]), "+f"(d[3])
        : "r"(a0), "r"(a1), "r"(a2), "r"(a3), "r"(b0), "r"(b1));
}

__device__ __forceinline__ void ldsm_x4(uint32_t& r0, uint32_t& r1,
                                        uint32_t& r2, uint32_t& r3, uint32_t addr) {
    asm volatile("ldmatrix.sync.aligned.m8n8.x4.shared.b16 {%0,%1,%2,%3}, [%4];"
                 : "=r"(r0), "=r"(r1), "=r"(r2), "=r"(r3) : "r"(addr));
}

// packed fp32x2 FMA: d = a*b + d (element-wise on 2 floats)
__device__ __forceinline__ void fma2(uint64_t& d, uint64_t a, uint64_t b) {
    asm("fma.rn.f32x2 %0, %1, %2, %0;" : "+l"(d) : "l"(a), "l"(b));
}
__device__ __forceinline__ uint64_t pk2(float lo, float hi) {
    uint64_t r;
    asm("mov.b64 %0, {%1, %2};" : "=l"(r) : "f"(lo), "f"(hi));
    return r;
}
__device__ __forceinline__ float up2sum(uint64_t v) {
    float lo, hi;
    asm("mov.b64 {%0, %1}, %2;" : "=f"(lo), "=f"(hi) : "l"(v));
    return lo + hi;
}

__device__ __forceinline__ float fast_tanh(float v) {
    float y;
    asm("tanh.approx.f32 %0, %1;" : "=f"(y) : "f"(v));
    return y;
}
__device__ __forceinline__ float fast_sig(float v) {
    return fmaf(fast_tanh(0.5f * v), 0.5f, 0.5f);
}

// ---------------------------------------------------------------------------
// Kernel 0: noop (launch-order padding for ncu sampling: period 3)
// ---------------------------------------------------------------------------
__global__ void noop_kernel() {}

// ---------------------------------------------------------------------------
// Kernel 1: projection GEMM xproj = x @ W via HMMA bf16, 3-term hi/lo split.
//   288 CTAs x 256 threads; 3 N-groups: group g covers n-tiles [8g, 8g+9)
//   (tiles 8,16 duplicated - identical stores). Each warp owns an m32 tile:
//   B fragments (one ldsm.x4 = hi+lo) are REUSED across 2 m16 halves,
//   halving L1 ldmatrix traffic per MMA. 39.2KB smem -> 2 CTAs/SM.
// ---------------------------------------------------------------------------
#define NT 9                         // n-tiles per CTA group
#define NBROWS (NT * 8)              // 72 B rows staged
#define KP 136                       // padded B row stride in bf16
#define BROW (KP * 2)                // 272 bytes
#define SMB_LO (NBROWS * BROW)       // 19584
#define SMB_TOTAL (2 * NBROWS * BROW)// 39168 bytes

__global__ __launch_bounds__(256, 2)
void proj_kernel(const float* __restrict__ x, const float* __restrict__ W) {
    extern __shared__ char smem[];
    const uint32_t sb = smem_u32(smem);
    const int tid = threadIdx.x;
    const int wid = tid >> 5;
    const int lane = tid & 31;
    const int grpN = blockIdx.x % 3;
    const int noff = grpN * 64;       // global n float-offset of this slice

    // Stage B = W^T hi/lo (rounding split) for n in [noff, noff+72).
    for (int idx = tid; idx < NBROWS * FF; idx += 256) {
        int nl = idx >> 7;
        int k = idx & 127;
        float v = W[k * GG + (noff + nl)];
        __nv_bfloat16 hi = __float2bfloat16_rn(v);
        float lo = v - __bfloat162float(hi);
        uint32_t off = (uint32_t)(nl * BROW + k * 2);
        *reinterpret_cast<__nv_bfloat16*>(smem + off) = hi;
        *reinterpret_cast<__nv_bfloat16*>(smem + SMB_LO + off) = __float2bfloat16_rn(lo);
    }
    __syncthreads();

    // ldmatrix.x4 lane addressing: 8-lane groups -> (hi k0, hi k8, lo k0, lo k8)
    const int l8 = lane & 7;
    const int grp = lane >> 3;
    const uint32_t lmOff = (uint32_t)(l8 * BROW + (grp & 1) * 16 + (grp >> 1) * SMB_LO);

    const int r = lane >> 2;     // 0..7  (fragment row)
    const int cq = lane & 3;     // 0..3  (fragment col quad)

    for (int mt = (blockIdx.x / 3) * 8 + wid; mt < MT32; mt += WSTRIDE_P) {
        const size_t row0 = (size_t)mt * 32 + r;

        const float* __restrict__ p0 = x + row0 * FF;         // rows r, r+8
        const float* __restrict__ p1 = x + (row0 + 8) * FF;
        const float* __restrict__ p2 = x + (row0 + 16) * FF;  // rows r+16, r+24
        const float* __restrict__ p3 = x + (row0 + 24) * FF;

        float acc0[NT][4], acc1[NT][4];
#pragma unroll
        for (int j = 0; j < NT; ++j) {
#pragma unroll
            for (int q = 0; q < 4; ++q) { acc0[j][q] = 0.f; acc1[j][q] = 0.f; }
        }

#pragma unroll
        for (int kk = 0; kk < 8; ++kk) {
            const int k0 = kk * 16;
            // A fragments for both m16 halves
            float2 f0 = *(const float2*)(p0 + k0 + 2 * cq);
            float2 f1 = *(const float2*)(p1 + k0 + 2 * cq);
            float2 f2 = *(const float2*)(p0 + k0 + 2 * cq + 8);
            float2 f3 = *(const float2*)(p1 + k0 + 2 * cq + 8);
            float2 g0 = *(const float2*)(p2 + k0 + 2 * cq);
            float2 g1 = *(const float2*)(p3 + k0 + 2 * cq);
            float2 g2 = *(const float2*)(p2 + k0 + 2 * cq + 8);
            float2 g3 = *(const float2*)(p3 + k0 + 2 * cq + 8);

            uint32_t ah0 = hipack(f0.x, f0.y), ah1 = hipack(f1.x, f1.y);
            uint32_t ah2 = hipack(f2.x, f2.y), ah3 = hipack(f3.x, f3.y);
            uint32_t al0 = bf2pack(f0.x - trunc_hi(f0.x), f0.y - trunc_hi(f0.y));
            uint32_t al1 = bf2pack(f1.x - trunc_hi(f1.x), f1.y - trunc_hi(f1.y));
            uint32_t al2 = bf2pack(f2.x - trunc_hi(f2.x), f2.y - trunc_hi(f2.y));
            uint32_t al3 = bf2pack(f3.x - trunc_hi(f3.x), f3.y - trunc_hi(f3.y));

            uint32_t bh0_ = hipack(g0.x, g0.y), bh1_ = hipack(g1.x, g1.y);
            uint32_t bh2_ = hipack(g2.x, g2.y), bh3_ = hipack(g3.x, g3.y);
            uint32_t bl0_ = bf2pack(g0.x - trunc_hi(g0.x), g0.y - trunc_hi(g0.y));
            uint32_t bl1_ = bf2pack(g1.x - trunc_hi(g1.x), g1.y - trunc_hi(g1.y));
            uint32_t bl2_ = bf2pack(g2.x - trunc_hi(g2.x), g2.y - trunc_hi(g2.y));
            uint32_t bl3_ = bf2pack(g3.x - trunc_hi(g3.x), g3.y - trunc_hi(g3.y));

            const uint32_t kOff = sb + (uint32_t)(k0 * 2) + lmOff;
#pragma unroll
            for (int j = 0; j < NT; ++j) {
                uint32_t wh0, wh1, wl0, wl1;
                ldsm_x4(wh0, wh1, wl0, wl1, kOff + (uint32_t)(j * 8 * BROW));
                mma16816(acc0[j], ah0, ah1, ah2, ah3, wh0, wh1);
                mma16816(acc0[j], ah0, ah1, ah2, ah3, wl0, wl1);
                mma16816(acc0[j], al0, al1, al2, al3, wh0, wh1);
                mma16816(acc1[j], bh0_, bh1_, bh2_, bh3_, wh0, wh1);
                mma16816(acc1[j], bh0_, bh1_, bh2_, bh3_, wl0, wl1);
                mma16816(acc1[j], bl0_, bl1_, bl2_, bl3_, wh0, wh1);
            }
        }

        float* __restrict__ d0 = g_xproj + row0 * GG + noff + 2 * cq;
        float* __restrict__ d1 = d0 + 8 * GG;
        float* __restrict__ d2 = d0 + 16 * GG;
        float* __restrict__ d3 = d0 + 24 * GG;
#pragma unroll
        for (int j = 0; j < NT; ++j) {
            *(float2*)(d0 + j * 8) = make_float2(acc0[j][0], acc0[j][1]);
            *(float2*)(d1 + j * 8) = make_float2(acc0[j][2], acc0[j][3]);
            *(float2*)(d2 + j * 8) = make_float2(acc1[j][0], acc1[j][1]);
            *(float2*)(d3 + j * 8) = make_float2(acc1[j][2], acc1[j][3]);
        }
    }
}

// ---------------------------------------------------------------------------
// Kernel 2: LSTM recurrence, two-row phase-interleaved (1 barrier/row-step).
//   256 CTAs x 288 threads, 2 rows (A,B) per CTA, 2 CTAs/SM single wave.
//   tid<200: gate-dot warps (warps 0-6, lanes 192-199 only in warp 6).
//   tid 224-273: update warps (warps 7-8) own c-state for both rows.
//   Phase even: dot A_t  || update B_{t-1};  Phase odd: dot B_t || update A_t.
// ---------------------------------------------------------------------------
__device__ __forceinline__ float dot50(const float* __restrict__ hs,
                                       const uint64_t* __restrict__ rw2) {
    uint64_t z2 = pk2(0.f, 0.f);
    uint64_t a0 = z2, a1 = z2, a2 = z2, a3 = z2;
#pragma unroll
    for (int i = 0; i < 6; ++i) {
        ulonglong2 hx = *(const ulonglong2*)(hs + 8 * i);
        ulonglong2 hy = *(const ulonglong2*)(hs + 8 * i + 4);
        fma2(a0, rw2[4 * i + 0], hx.x);
        fma2(a1, rw2[4 * i + 1], hx.y);
        fma2(a2, rw2[4 * i + 2], hy.x);
        fma2(a3, rw2[4 * i + 3], hy.y);
    }
    fma2(a0, rw2[24], *(const uint64_t*)(hs + 48));
    return (up2sum(a0) + up2sum(a1)) + (up2sum(a2) + up2sum(a3));
}

__global__ __launch_bounds__(288, 2)
void lstm_kernel(const float* __restrict__ R, const float* __restrict__ bias,
                 const float* __restrict__ dw, const float* __restrict__ db,
                 float* __restrict__ out) {
    __shared__ __align__(16) float hA_s[52];
    __shared__ __align__(16) float hB_s[52];
    __shared__ float zA_s[200];
    __shared__ float zB_s[200];

    const int tid = threadIdx.x;
    const int b0 = blockIdx.x * 2;
    const int b1 = b0 + 1;
    const bool isDot = (tid < GG);
    const bool isUpd = (tid >= 224 && tid < 224 + UU);
    const int uu = tid - 224;

    uint64_t rw2[25];
    float bv = 0.f;
    if (isDot) {
#pragma unroll
        for (int u2 = 0; u2 < 25; ++u2)
            rw2[u2] = pk2(R[(2 * u2) * GG + tid], R[(2 * u2 + 1) * GG + tid]);
        bv = bias[tid];
    }
    if (tid < 52) { hA_s[tid] = 0.f; hB_s[tid] = 0.f; }
    float cA = 0.f, cB = 0.f;
    __syncthreads();

    const float* __restrict__ xpA = g_xproj + (size_t)b0 * TT * GG;
    const float* __restrict__ xpB = g_xproj + (size_t)b1 * TT * GG;

    float xA0 = 0.f, xA1 = 0.f, xB0 = 0.f, xB1 = 0.f;
    if (isDot) {
        xA0 = __ldcs(xpA + tid);       xB0 = __ldcs(xpB + tid);
        xA1 = __ldcs(xpA + GG + tid);  xB1 = __ldcs(xpB + GG + tid);
    }

#pragma unroll 1
    for (int t = 0; t < TT; ++t) {
        float xA2 = 0.f, xB2 = 0.f;
        const bool isg = (tid >= 100 && tid < 150);

        // ---- even phase: dot A_t  ||  update B_{t-1} ----
        if (isDot) {
            int tn = (t + 2 < TT) ? (t + 2) : (TT - 1);
            xA2 = __ldcs(xpA + (size_t)tn * GG + tid);
            float acc = dot50(hA_s, rw2) + (bv + xA0);
            zA_s[tid] = isg ? fast_tanh(acc) : fast_sig(acc);
        } else if (isUpd && t > 0) {
            float gi = zB_s[uu], gf = zB_s[uu + 50];
            float gg = zB_s[uu + 100], go = zB_s[uu + 150];
            cB = fmaf(gf, cB, gi * gg);
            hB_s[uu] = go * fast_tanh(cB);
        }
        __syncthreads();

        // ---- odd phase: dot B_t  ||  update A_t ----
        if (isDot) {
            int tn = (t + 2 < TT) ? (t + 2) : (TT - 1);
            xB2 = __ldcs(xpB + (size_t)tn * GG + tid);
            float acc = dot50(hB_s, rw2) + (bv + xB0);
            zB_s[tid] = isg ? fast_tanh(acc) : fast_sig(acc);
            xA0 = xA1; xA1 = xA2;
            xB0 = xB1; xB1 = xB2;
        } else if (isUpd) {
            float gi = zA_s[uu], gf = zA_s[uu + 50];
            float gg = zA_s[uu + 100], go = zA_s[uu + 150];
            cA = fmaf(gf, cA, gi * gg);
            hA_s[uu] = go * fast_tanh(cA);
        }
        __syncthreads();
    }

    // epilogue: update B_{TT-1}
    if (isUpd) {
        float gi = zB_s[uu], gf = zB_s[uu + 50];
        float gg = zB_s[uu + 100], go = zB_s[uu + 150];
        cB = fmaf(gf, cB, gi * gg);
        hB_s[uu] = go * fast_tanh(cB);
    }
    __syncthreads();

    // dense head
    if (tid == 0) {
        float s = db[0];
#pragma unroll
        for (int u = 0; u < UU; ++u) s += hA_s[u] * dw[u];
        out[b0] = s;
    } else if (tid == 32) {
        float s = db[0];
#pragma unroll
        for (int u = 0; u < UU; ++u) s += hB_s[u] * dw[u];
        out[b1] = s;
    }
}

// ---------------------------------------------------------------------------
extern "C" void kernel_launch(void* const* d_in, const int* in_sizes, int n_in,
                              void* d_out, int out_size) {
    const float* x    = (const float*)d_in[0];  // [512,1024,128]
    const float* W    = (const float*)d_in[1];  // [128,200]
    const float* R    = (const float*)d_in[2];  // [50,200]
    const float* bias = (const float*)d_in[3];  // [200]
    const float* dw   = (const float*)d_in[4];  // [50]
    const float* db   = (const float*)d_in[5];  // [1]
    float* out = (float*)d_out;                 // [512]
    (void)in_sizes; (void)n_in; (void)out_size;

    cudaFuncSetAttribute(proj_kernel,
                         cudaFuncAttributeMaxDynamicSharedMemorySize, SMB_TOTAL);

    // Launch period = 3 (sampler empirically lands on the first of each triple)
    proj_kernel<<<NCTA_P, 256, SMB_TOTAL>>>(x, W);
    lstm_kernel<<<BB / 2, 288>>>(R, bias, dw, db, out);
    noop_kernel<<<1, 32>>>();
}

// round 10
// speedup vs baseline: 1.3252x; 1.3252x over previous
#include <cuda_runtime.h>
#include <cuda_bf16.h>
#include <math.h>
#include <stdint.h>

// Problem constants
#define BB 512
#define TT 1024
#define FF 128
#define UU 50
#define GG 200            // 4*U gate columns
#define NROWS (BB * TT)   // 524288 GEMM rows
#define MT32 (NROWS / 32) // 16384 m32 tiles
#define NCTA_P 288        // proj CTAs (2 per SM, 3 N-groups x 96)
#define WSTRIDE_P (96 * 8)// m32-tile warp stride per N-group

// Scratch: xproj[b*T + t][200] = x[b,t,:] @ kernel (fp32)
__device__ float g_xproj[(size_t)NROWS * GG];

// ---------------------------------------------------------------------------
// helpers
// ---------------------------------------------------------------------------
__device__ __forceinline__ uint32_t smem_u32(const void* p) {
    uint32_t a;
    asm("{ .reg .u64 t; cvta.to.shared.u64 t, %1; cvt.u32.u64 %0, t; }" : "=r"(a) : "l"(p));
    return a;
}

__device__ __forceinline__ uint32_t bf2pack(float a, float b) {
    __nv_bfloat162 t = __floats2bfloat162_rn(a, b);
    return *reinterpret_cast<uint32_t*>(&t);
}

// pack top 16 bits of two floats into bf16x2 (truncation split, 1 instr)
__device__ __forceinline__ uint32_t hipack(float a, float b) {
    uint32_t d;
    asm("prmt.b32 %0, %1, %2, 0x7632;" : "=r"(d)
        : "r"(__float_as_uint(a)), "r"(__float_as_uint(b)));
    return d;
}
__device__ __forceinline__ float trunc_hi(float v) {
    return __uint_as_float(__float_as_uint(v) & 0xffff0000u);
}

__device__ __forceinline__ void mma16816(float* d, uint32_t a0, uint32_t a1,
                                         uint32_t a2, uint32_t a3,
                                         uint32_t b0, uint32_t b1) {
    asm volatile(
        "mma.sync.aligned.m16n8k16.row.col.f32.bf16.bf16.f32 "
        "{%0,%1,%2,%3}, {%4,%5,%6,%7}, {%8,%9}, {%0,%1,%2,%3};"
        : "+f"(d[0]), "+f"(d[1]), "+f"(d[2]), "+f"(d[3])
        : "r"(a0), "r"(a1), "r"(a2), "r"(a3), "r"(b0), "r"(b1));
}

__device__ __forceinline__ void ldsm_x4(uint32_t& r0, uint32_t& r1,
                                        uint32_t& r2, uint32_t& r3, uint32_t addr) {
    asm volatile("ldmatrix.sync.aligned.m8n8.x4.shared.b16 {%0,%1,%2,%3}, [%4];"
                 : "=r"(r0), "=r"(r1), "=r"(r2), "=r"(r3) : "r"(addr));
}

// packed fp32x2 FMA: d = a*b + d (element-wise on 2 floats)
__device__ __forceinline__ void fma2(uint64_t& d, uint64_t a, uint64_t b) {
    asm("fma.rn.f32x2 %0, %1, %2, %0;" : "+l"(d) : "l"(a), "l"(b));
}
__device__ __forceinline__ uint64_t pk2(float lo, float hi) {
    uint64_t r;
    asm("mov.b64 %0, {%1, %2};" : "=l"(r) : "f"(lo), "f"(hi));
    return r;
}
__device__ __forceinline__ float up2sum(uint64_t v) {
    float lo, hi;
    asm("mov.b64 {%0, %1}, %2;" : "=f"(lo), "=f"(hi) : "l"(v));
    return lo + hi;
}

__device__ __forceinline__ float fast_tanh(float v) {
    float y;
    asm("tanh.approx.f32 %0, %1;" : "=f"(y) : "f"(v));
    return y;
}
__device__ __forceinline__ float fast_sig(float v) {
    return fmaf(fast_tanh(0.5f * v), 0.5f, 0.5f);
}

// ---------------------------------------------------------------------------
// Kernel 1: projection GEMM xproj = x @ W via HMMA bf16, 3-term hi/lo split.
//   288 CTAs x 256 threads; 3 N-groups: group g covers n-tiles [8g, 8g+9)
//   (tiles 8,16 duplicated - identical stores). Each warp owns an m32 tile:
//   B fragments (one ldsm.x4 = hi+lo) REUSED across 2 m16 halves.
//   39.2KB smem -> 2 CTAs/SM.  [R9-measured: 278.8us, tensor 57%]
// ---------------------------------------------------------------------------
#define NT 9                         // n-tiles per CTA group
#define NBROWS (NT * 8)              // 72 B rows staged
#define KP 136                       // padded B row stride in bf16
#define BROW (KP * 2)                // 272 bytes
#define SMB_LO (NBROWS * BROW)       // 19584
#define SMB_TOTAL (2 * NBROWS * BROW)// 39168 bytes

__global__ __launch_bounds__(256, 2)
void proj_kernel(const float* __restrict__ x, const float* __restrict__ W) {
    extern __shared__ char smem[];
    const uint32_t sb = smem_u32(smem);
    const int tid = threadIdx.x;
    const int wid = tid >> 5;
    const int lane = tid & 31;
    const int grpN = blockIdx.x % 3;
    const int noff = grpN * 64;       // global n float-offset of this slice

    // Stage B = W^T hi/lo (rounding split) for n in [noff, noff+72).
    for (int idx = tid; idx < NBROWS * FF; idx += 256) {
        int nl = idx >> 7;
        int k = idx & 127;
        float v = W[k * GG + (noff + nl)];
        __nv_bfloat16 hi = __float2bfloat16_rn(v);
        float lo = v - __bfloat162float(hi);
        uint32_t off = (uint32_t)(nl * BROW + k * 2);
        *reinterpret_cast<__nv_bfloat16*>(smem + off) = hi;
        *reinterpret_cast<__nv_bfloat16*>(smem + SMB_LO + off) = __float2bfloat16_rn(lo);
    }
    __syncthreads();

    // ldmatrix.x4 lane addressing: 8-lane groups -> (hi k0, hi k8, lo k0, lo k8)
    const int l8 = lane & 7;
    const int grp = lane >> 3;
    const uint32_t lmOff = (uint32_t)(l8 * BROW + (grp & 1) * 16 + (grp >> 1) * SMB_LO);

    const int r = lane >> 2;     // 0..7  (fragment row)
    const int cq = lane & 3;     // 0..3  (fragment col quad)

    for (int mt = (blockIdx.x / 3) * 8 + wid; mt < MT32; mt += WSTRIDE_P) {
        const size_t row0 = (size_t)mt * 32 + r;

        const float* __restrict__ p0 = x + row0 * FF;         // rows r, r+8
        const float* __restrict__ p1 = x + (row0 + 8) * FF;
        const float* __restrict__ p2 = x + (row0 + 16) * FF;  // rows r+16, r+24
        const float* __restrict__ p3 = x + (row0 + 24) * FF;

        float acc0[NT][4], acc1[NT][4];
#pragma unroll
        for (int j = 0; j < NT; ++j) {
#pragma unroll
            for (int q = 0; q < 4; ++q) { acc0[j][q] = 0.f; acc1[j][q] = 0.f; }
        }

#pragma unroll
        for (int kk = 0; kk < 8; ++kk) {
            const int k0 = kk * 16;
            float2 f0 = *(const float2*)(p0 + k0 + 2 * cq);
            float2 f1 = *(const float2*)(p1 + k0 + 2 * cq);
            float2 f2 = *(const float2*)(p0 + k0 + 2 * cq + 8);
            float2 f3 = *(const float2*)(p1 + k0 + 2 * cq + 8);
            float2 g0 = *(const float2*)(p2 + k0 + 2 * cq);
            float2 g1 = *(const float2*)(p3 + k0 + 2 * cq);
            float2 g2 = *(const float2*)(p2 + k0 + 2 * cq + 8);
            float2 g3 = *(const float2*)(p3 + k0 + 2 * cq + 8);

            uint32_t ah0 = hipack(f0.x, f0.y), ah1 = hipack(f1.x, f1.y);
            uint32_t ah2 = hipack(f2.x, f2.y), ah3 = hipack(f3.x, f3.y);
            uint32_t al0 = bf2pack(f0.x - trunc_hi(f0.x), f0.y - trunc_hi(f0.y));
            uint32_t al1 = bf2pack(f1.x - trunc_hi(f1.x), f1.y - trunc_hi(f1.y));
            uint32_t al2 = bf2pack(f2.x - trunc_hi(f2.x), f2.y - trunc_hi(f2.y));
            uint32_t al3 = bf2pack(f3.x - trunc_hi(f3.x), f3.y - trunc_hi(f3.y));

            uint32_t bh0_ = hipack(g0.x, g0.y), bh1_ = hipack(g1.x, g1.y);
            uint32_t bh2_ = hipack(g2.x, g2.y), bh3_ = hipack(g3.x, g3.y);
            uint32_t bl0_ = bf2pack(g0.x - trunc_hi(g0.x), g0.y - trunc_hi(g0.y));
            uint32_t bl1_ = bf2pack(g1.x - trunc_hi(g1.x), g1.y - trunc_hi(g1.y));
            uint32_t bl2_ = bf2pack(g2.x - trunc_hi(g2.x), g2.y - trunc_hi(g2.y));
            uint32_t bl3_ = bf2pack(g3.x - trunc_hi(g3.x), g3.y - trunc_hi(g3.y));

            const uint32_t kOff = sb + (uint32_t)(k0 * 2) + lmOff;
#pragma unroll
            for (int j = 0; j < NT; ++j) {
                uint32_t wh0, wh1, wl0, wl1;
                ldsm_x4(wh0, wh1, wl0, wl1, kOff + (uint32_t)(j * 8 * BROW));
                mma16816(acc0[j], ah0, ah1, ah2, ah3, wh0, wh1);
                mma16816(acc0[j], ah0, ah1, ah2, ah3, wl0, wl1);
                mma16816(acc0[j], al0, al1, al2, al3, wh0, wh1);
                mma16816(acc1[j], bh0_, bh1_, bh2_, bh3_, wh0, wh1);
                mma16816(acc1[j], bh0_, bh1_, bh2_, bh3_, wl0, wl1);
                mma16816(acc1[j], bl0_, bl1_, bl2_, bl3_, wh0, wh1);
            }
        }

        float* __restrict__ d0 = g_xproj + row0 * GG + noff + 2 * cq;
        float* __restrict__ d1 = d0 + 8 * GG;
        float* __restrict__ d2 = d0 + 16 * GG;
        float* __restrict__ d3 = d0 + 24 * GG;
#pragma unroll
        for (int j = 0; j < NT; ++j) {
            *(float2*)(d0 + j * 8) = make_float2(acc0[j][0], acc0[j][1]);
            *(float2*)(d1 + j * 8) = make_float2(acc0[j][2], acc0[j][3]);
            *(float2*)(d2 + j * 8) = make_float2(acc1[j][0], acc1[j][1]);
            *(float2*)(d3 + j * 8) = make_float2(acc1[j][2], acc1[j][3]);
        }
    }
}

// ---------------------------------------------------------------------------
// Kernel 2: persistent LSTM recurrence + dense head (R8 design, reverted).
//   1 row/CTA, 512 CTAs x 224 threads, 4 CTAs/SM. f32x2 packed dot,
//   tanh.approx gates, 1-step __ldcs prefetch. z stored INTERLEAVED
//   (z_s[u*4+gate]) so the update phase reads one LDS.128 per thread.
// ---------------------------------------------------------------------------
__global__ __launch_bounds__(224, 4)
void lstm_kernel(const float* __restrict__ R, const float* __restrict__ bias,
                 const float* __restrict__ dw, const float* __restrict__ db,
                 float* __restrict__ out) {
    __shared__ __align__(16) float h_s[52];
    __shared__ __align__(16) float z_s[200];   // interleaved [u][gate]

    const int tid = threadIdx.x;
    const int b = blockIdx.x;
    const int gate = tid / 50;        // 0=i,1=f,2=g,3=o (tid<200)
    const int uidx = tid - gate * 50; // u within gate

    uint64_t rw2[25];      // packed rec_kernel column pairs (u, u+1)
    float bv = 0.f;
    if (tid < GG) {
#pragma unroll
        for (int u2 = 0; u2 < 25; ++u2)
            rw2[u2] = pk2(R[(2 * u2) * GG + tid], R[(2 * u2 + 1) * GG + tid]);
        bv = bias[tid];
    }
    if (tid < 52) h_s[tid] = 0.f;
    float c = 0.f;
    __syncthreads();

    const float* __restrict__ xp = g_xproj + (size_t)b * TT * GG;
    float xv = (tid < GG) ? __ldcs(xp + tid) : 0.f;

#pragma unroll 1
    for (int t = 0; t < TT; ++t) {
        float xn = 0.f;
        if (tid < GG) {
            int tn = (t + 1 < TT) ? (t + 1) : (TT - 1);
            xn = __ldcs(xp + (size_t)tn * GG + tid);   // prefetch next step

            // z = h_{t-1} . rec_col via packed f32x2 (4 independent chains)
            uint64_t z2 = pk2(0.f, 0.f);
            uint64_t acc2[4] = {z2, z2, z2, z2};
#pragma unroll
            for (int i = 0; i < 12; ++i) {
                ulonglong2 h2 = *(const ulonglong2*)(h_s + 4 * i);  // pairs 2i, 2i+1
                fma2(acc2[(2 * i) & 3], rw2[2 * i], h2.x);
                fma2(acc2[(2 * i + 1) & 3], rw2[2 * i + 1], h2.y);
            }
            fma2(acc2[0], rw2[24], *(const uint64_t*)(h_s + 48));   // pair 24
            float acc = (up2sum(acc2[0]) + up2sum(acc2[1])) +
                        (up2sum(acc2[2]) + up2sum(acc2[3])) + (bv + xv);

            z_s[uidx * 4 + gate] = (gate == 2) ? fast_tanh(acc) : fast_sig(acc);
        }
        __syncthreads();
        if (tid < UU) {
            float4 z4 = *(const float4*)(z_s + 4 * tid);  // i,f,g,o
            c = fmaf(z4.y, c, z4.x * z4.z);
            h_s[tid] = z4.w * fast_tanh(c);
        }
        __syncthreads();
        xv = xn;
    }

    // dense head: out[b] = h . dense_w + dense_b
    if (tid == 0) {
        float s = db[0];
#pragma unroll
        for (int u = 0; u < UU; ++u) s += h_s[u] * dw[u];
        out[b] = s;
    }
}

// ---------------------------------------------------------------------------
extern "C" void kernel_launch(void* const* d_in, const int* in_sizes, int n_in,
                              void* d_out, int out_size) {
    const float* x    = (const float*)d_in[0];  // [512,1024,128]
    const float* W    = (const float*)d_in[1];  // [128,200]
    const float* R    = (const float*)d_in[2];  // [50,200]
    const float* bias = (const float*)d_in[3];  // [200]
    const float* dw   = (const float*)d_in[4];  // [50]
    const float* db   = (const float*)d_in[5];  // [1]
    float* out = (float*)d_out;                 // [512]
    (void)in_sizes; (void)n_in; (void)out_size;

    cudaFuncSetAttribute(proj_kernel,
                         cudaFuncAttributeMaxDynamicSharedMemorySize, SMB_TOTAL);

    // Launch period = 2: sampled launch index 3 -> lstm gets profiled.
    proj_kernel<<<NCTA_P, 256, SMB_TOTAL>>>(x, W);
    lstm_kernel<<<BB, 224>>>(R, bias, dw, db, out);
}

// round 11
// speedup vs baseline: 1.4555x; 1.0983x over previous
#include <cuda_runtime.h>
#include <cuda_bf16.h>
#include <math.h>
#include <stdint.h>

// Problem constants
#define BB 512
#define TT 1024
#define FF 128
#define UU 50
#define GG 200            // 4*U gate columns
#define NROWS (BB * TT)   // 524288 GEMM rows
#define MT32 (NROWS / 32) // 16384 m32 tiles
#define NCTA_P 288        // proj CTAs (2 per SM, 3 N-groups x 96)
#define WSTRIDE_P (96 * 8)// m32-tile warp stride per N-group

// Scratch: xproj[b*T + t][200] = x[b,t,:] @ kernel (fp32)
__device__ float g_xproj[(size_t)NROWS * GG];

// ---------------------------------------------------------------------------
// helpers
// ---------------------------------------------------------------------------
__device__ __forceinline__ uint32_t smem_u32(const void* p) {
    uint32_t a;
    asm("{ .reg .u64 t; cvta.to.shared.u64 t, %1; cvt.u32.u64 %0, t; }" : "=r"(a) : "l"(p));
    return a;
}

__device__ __forceinline__ uint32_t bf2pack(float a, float b) {
    __nv_bfloat162 t = __floats2bfloat162_rn(a, b);
    return *reinterpret_cast<uint32_t*>(&t);
}

// pack top 16 bits of two floats into bf16x2 (truncation split, 1 instr)
__device__ __forceinline__ uint32_t hipack(float a, float b) {
    uint32_t d;
    asm("prmt.b32 %0, %1, %2, 0x7632;" : "=r"(d)
        : "r"(__float_as_uint(a)), "r"(__float_as_uint(b)));
    return d;
}
__device__ __forceinline__ float trunc_hi(float v) {
    return __uint_as_float(__float_as_uint(v) & 0xffff0000u);
}

__device__ __forceinline__ void mma16816(float* d, uint32_t a0, uint32_t a1,
                                         uint32_t a2, uint32_t a3,
                                         uint32_t b0, uint32_t b1) {
    asm volatile(
        "mma.sync.aligned.m16n8k16.row.col.f32.bf16.bf16.f32 "
        "{%0,%1,%2,%3}, {%4,%5,%6,%7}, {%8,%9}, {%0,%1,%2,%3};"
        : "+f"(d[0]), "+f"(d[1]), "+f"(d[2]), "+f"(d[3])
        : "r"(a0), "r"(a1), "r"(a2), "r"(a3), "r"(b0), "r"(b1));
}

__device__ __forceinline__ void ldsm_x4(uint32_t& r0, uint32_t& r1,
                                        uint32_t& r2, uint32_t& r3, uint32_t addr) {
    asm volatile("ldmatrix.sync.aligned.m8n8.x4.shared.b16 {%0,%1,%2,%3}, [%4];"
                 : "=r"(r0), "=r"(r1), "=r"(r2), "=r"(r3) : "r"(addr));
}

// packed fp32x2 FMA: d = a*b + d (element-wise on 2 floats)
__device__ __forceinline__ void fma2(uint64_t& d, uint64_t a, uint64_t b) {
    asm("fma.rn.f32x2 %0, %1, %2, %0;" : "+l"(d) : "l"(a), "l"(b));
}
__device__ __forceinline__ uint64_t pk2(float lo, float hi) {
    uint64_t r;
    asm("mov.b64 %0, {%1, %2};" : "=l"(r) : "f"(lo), "f"(hi));
    return r;
}
__device__ __forceinline__ float up2sum(uint64_t v) {
    float lo, hi;
    asm("mov.b64 {%0, %1}, %2;" : "=f"(lo), "=f"(hi) : "l"(v));
    return lo + hi;
}

__device__ __forceinline__ float fast_tanh(float v) {
    float y;
    asm("tanh.approx.f32 %0, %1;" : "=f"(y) : "f"(v));
    return y;
}
__device__ __forceinline__ float fast_sig(float v) {
    return fmaf(fast_tanh(0.5f * v), 0.5f, 0.5f);
}

// ---------------------------------------------------------------------------
// Kernel 1: projection GEMM xproj = x @ W via HMMA bf16, 3-term hi/lo split.
//   288 CTAs x 256 threads; 3 N-groups; each warp owns an m32 tile with
//   B-fragment reuse across the two m16 halves. [R9-measured: 278.8us]
// ---------------------------------------------------------------------------
#define NT 9                         // n-tiles per CTA group
#define NBROWS (NT * 8)              // 72 B rows staged
#define KP 136                       // padded B row stride in bf16
#define BROW (KP * 2)                // 272 bytes
#define SMB_LO (NBROWS * BROW)       // 19584
#define SMB_TOTAL (2 * NBROWS * BROW)// 39168 bytes

__global__ __launch_bounds__(256, 2)
void proj_kernel(const float* __restrict__ x, const float* __restrict__ W) {
    extern __shared__ char smem[];
    const uint32_t sb = smem_u32(smem);
    const int tid = threadIdx.x;
    const int wid = tid >> 5;
    const int lane = tid & 31;
    const int grpN = blockIdx.x % 3;
    const int noff = grpN * 64;       // global n float-offset of this slice

    for (int idx = tid; idx < NBROWS * FF; idx += 256) {
        int nl = idx >> 7;
        int k = idx & 127;
        float v = W[k * GG + (noff + nl)];
        __nv_bfloat16 hi = __float2bfloat16_rn(v);
        float lo = v - __bfloat162float(hi);
        uint32_t off = (uint32_t)(nl * BROW + k * 2);
        *reinterpret_cast<__nv_bfloat16*>(smem + off) = hi;
        *reinterpret_cast<__nv_bfloat16*>(smem + SMB_LO + off) = __float2bfloat16_rn(lo);
    }
    __syncthreads();

    const int l8 = lane & 7;
    const int grp = lane >> 3;
    const uint32_t lmOff = (uint32_t)(l8 * BROW + (grp & 1) * 16 + (grp >> 1) * SMB_LO);

    const int r = lane >> 2;
    const int cq = lane & 3;

    for (int mt = (blockIdx.x / 3) * 8 + wid; mt < MT32; mt += WSTRIDE_P) {
        const size_t row0 = (size_t)mt * 32 + r;

        const float* __restrict__ p0 = x + row0 * FF;
        const float* __restrict__ p1 = x + (row0 + 8) * FF;
        const float* __restrict__ p2 = x + (row0 + 16) * FF;
        const float* __restrict__ p3 = x + (row0 + 24) * FF;

        float acc0[NT][4], acc1[NT][4];
#pragma unroll
        for (int j = 0; j < NT; ++j) {
#pragma unroll
            for (int q = 0; q < 4; ++q) { acc0[j][q] = 0.f; acc1[j][q] = 0.f; }
        }

#pragma unroll
        for (int kk = 0; kk < 8; ++kk) {
            const int k0 = kk * 16;
            float2 f0 = *(const float2*)(p0 + k0 + 2 * cq);
            float2 f1 = *(const float2*)(p1 + k0 + 2 * cq);
            float2 f2 = *(const float2*)(p0 + k0 + 2 * cq + 8);
            float2 f3 = *(const float2*)(p1 + k0 + 2 * cq + 8);
            float2 g0 = *(const float2*)(p2 + k0 + 2 * cq);
            float2 g1 = *(const float2*)(p3 + k0 + 2 * cq);
            float2 g2 = *(const float2*)(p2 + k0 + 2 * cq + 8);
            float2 g3 = *(const float2*)(p3 + k0 + 2 * cq + 8);

            uint32_t ah0 = hipack(f0.x, f0.y), ah1 = hipack(f1.x, f1.y);
            uint32_t ah2 = hipack(f2.x, f2.y), ah3 = hipack(f3.x, f3.y);
            uint32_t al0 = bf2pack(f0.x - trunc_hi(f0.x), f0.y - trunc_hi(f0.y));
            uint32_t al1 = bf2pack(f1.x - trunc_hi(f1.x), f1.y - trunc_hi(f1.y));
            uint32_t al2 = bf2pack(f2.x - trunc_hi(f2.x), f2.y - trunc_hi(f2.y));
            uint32_t al3 = bf2pack(f3.x - trunc_hi(f3.x), f3.y - trunc_hi(f3.y));

            uint32_t bh0_ = hipack(g0.x, g0.y), bh1_ = hipack(g1.x, g1.y);
            uint32_t bh2_ = hipack(g2.x, g2.y), bh3_ = hipack(g3.x, g3.y);
            uint32_t bl0_ = bf2pack(g0.x - trunc_hi(g0.x), g0.y - trunc_hi(g0.y));
            uint32_t bl1_ = bf2pack(g1.x - trunc_hi(g1.x), g1.y - trunc_hi(g1.y));
            uint32_t bl2_ = bf2pack(g2.x - trunc_hi(g2.x), g2.y - trunc_hi(g2.y));
            uint32_t bl3_ = bf2pack(g3.x - trunc_hi(g3.x), g3.y - trunc_hi(g3.y));

            const uint32_t kOff = sb + (uint32_t)(k0 * 2) + lmOff;
#pragma unroll
            for (int j = 0; j < NT; ++j) {
                uint32_t wh0, wh1, wl0, wl1;
                ldsm_x4(wh0, wh1, wl0, wl1, kOff + (uint32_t)(j * 8 * BROW));
                mma16816(acc0[j], ah0, ah1, ah2, ah3, wh0, wh1);
                mma16816(acc0[j], ah0, ah1, ah2, ah3, wl0, wl1);
                mma16816(acc0[j], al0, al1, al2, al3, wh0, wh1);
                mma16816(acc1[j], bh0_, bh1_, bh2_, bh3_, wh0, wh1);
                mma16816(acc1[j], bh0_, bh1_, bh2_, bh3_, wl0, wl1);
                mma16816(acc1[j], bl0_, bl1_, bl2_, bl3_, wh0, wh1);
            }
        }

        float* __restrict__ d0 = g_xproj + row0 * GG + noff + 2 * cq;
        float* __restrict__ d1 = d0 + 8 * GG;
        float* __restrict__ d2 = d0 + 16 * GG;
        float* __restrict__ d3 = d0 + 24 * GG;
#pragma unroll
        for (int j = 0; j < NT; ++j) {
            *(float2*)(d0 + j * 8) = make_float2(acc0[j][0], acc0[j][1]);
            *(float2*)(d1 + j * 8) = make_float2(acc0[j][2], acc0[j][3]);
            *(float2*)(d2 + j * 8) = make_float2(acc1[j][0], acc1[j][1]);
            *(float2*)(d3 + j * 8) = make_float2(acc1[j][2], acc1[j][3]);
        }
    }
}

// ---------------------------------------------------------------------------
// Kernel 2: LSTM recurrence, shuffle-fused single-barrier step.
//   512 CTAs x 224 threads, 4 CTAs/SM. Thread (u = tid>>2, g = tid&3) owns
//   gate column g*50+u, so the 4 gates of unit u sit in ONE shuffle quad:
//   after activation, 4 shfl gather (i,f,g~,o); every quad lane redundantly
//   carries c_u and computes h_u. No z smem, no update phase. h is
//   double-buffered -> exactly 1 __syncthreads per timestep.
// ---------------------------------------------------------------------------
__device__ __forceinline__ float dot50(const float* __restrict__ hs,
                                       const uint64_t* __restrict__ rw2) {
    uint64_t z2 = pk2(0.f, 0.f);
    uint64_t a0 = z2, a1 = z2, a2 = z2, a3 = z2;
#pragma unroll
    for (int i = 0; i < 6; ++i) {
        ulonglong2 hx = *(const ulonglong2*)(hs + 8 * i);
        ulonglong2 hy = *(const ulonglong2*)(hs + 8 * i + 4);
        fma2(a0, rw2[4 * i + 0], hx.x);
        fma2(a1, rw2[4 * i + 1], hx.y);
        fma2(a2, rw2[4 * i + 2], hy.x);
        fma2(a3, rw2[4 * i + 3], hy.y);
    }
    fma2(a0, rw2[24], *(const uint64_t*)(hs + 48));
    return (up2sum(a0) + up2sum(a1)) + (up2sum(a2) + up2sum(a3));
}

__global__ __launch_bounds__(224, 4)
void lstm_kernel(const float* __restrict__ R, const float* __restrict__ bias,
                 const float* __restrict__ dw, const float* __restrict__ db,
                 float* __restrict__ out) {
    __shared__ __align__(16) float h_s[2][56];

    const int tid = threadIdx.x;
    const int b = blockIdx.x;
    const int g = tid & 3;            // gate: 0=i 1=f 2=g~ 3=o
    const int u = tid >> 2;           // unit (0..55; >=50 inactive)
    int col = g * 50 + u;             // gate column in [0,200) after clamp
    if (col > 199) col = 199;         // threads 220..223 read harmless data
    const int lane = tid & 31;
    const int q0 = lane & ~3;         // quad base lane
    const bool writer = (g == 0) && (u < UU);

    uint64_t rw2[25];                 // packed rec_kernel column pairs
#pragma unroll
    for (int u2 = 0; u2 < 25; ++u2)
        rw2[u2] = pk2(R[(2 * u2) * GG + col], R[(2 * u2 + 1) * GG + col]);
    const float bv = bias[col];

    if (tid < 56) { h_s[0][tid] = 0.f; h_s[1][tid] = 0.f; }
    float c = 0.f;
    __syncthreads();

    const float* __restrict__ xp = g_xproj + (size_t)b * TT * GG;
    float xv = __ldcs(xp + col);

#pragma unroll 1
    for (int t = 0; t < TT; ++t) {
        const float* hr = h_s[t & 1];
        float* hw = h_s[(t & 1) ^ 1];

        int tn = (t + 1 < TT) ? (t + 1) : (TT - 1);
        float xn = __ldcs(xp + (size_t)tn * GG + col);   // prefetch next step

        float acc = dot50(hr, rw2) + (bv + xv);
        float z = (g == 2) ? fast_tanh(acc) : fast_sig(acc);

        // gather the quad's 4 gate values
        float zi = __shfl_sync(0xFFFFFFFFu, z, q0 + 0);
        float zf = __shfl_sync(0xFFFFFFFFu, z, q0 + 1);
        float zg = __shfl_sync(0xFFFFFFFFu, z, q0 + 2);
        float zo = __shfl_sync(0xFFFFFFFFu, z, q0 + 3);

        c = fmaf(zf, c, zi * zg);
        float h = zo * fast_tanh(c);
        if (writer) hw[u] = h;

        __syncthreads();
        xv = xn;
    }

    // dense head: out[b] = h . dense_w + dense_b  (final h in buffer TT&1 = 0)
    if (tid == 0) {
        float s = db[0];
#pragma unroll
        for (int uu2 = 0; uu2 < UU; ++uu2) s += h_s[0][uu2] * dw[uu2];
        out[b] = s;
    }
}

// ---------------------------------------------------------------------------
extern "C" void kernel_launch(void* const* d_in, const int* in_sizes, int n_in,
                              void* d_out, int out_size) {
    const float* x    = (const float*)d_in[0];  // [512,1024,128]
    const float* W    = (const float*)d_in[1];  // [128,200]
    const float* R    = (const float*)d_in[2];  // [50,200]
    const float* bias = (const float*)d_in[3];  // [200]
    const float* dw   = (const float*)d_in[4];  // [50]
    const float* db   = (const float*)d_in[5];  // [1]
    float* out = (float*)d_out;                 // [512]
    (void)in_sizes; (void)n_in; (void)out_size;

    cudaFuncSetAttribute(proj_kernel,
                         cudaFuncAttributeMaxDynamicSharedMemorySize, SMB_TOTAL);

    // Launch period = 2: sampled launch index 3 -> lstm gets profiled.
    proj_kernel<<<NCTA_P, 256, SMB_TOTAL>>>(x, W);
    lstm_kernel<<<BB, 224>>>(R, bias, dw, db, out);
}

// round 12
// speedup vs baseline: 1.6765x; 1.1519x over previous
#include <cuda_runtime.h>
#include <cuda_bf16.h>
#include <math.h>
#include <stdint.h>

// Problem constants
#define BB 512
#define TT 1024
#define FF 128
#define UU 50
#define GG 200            // 4*U gate columns
#define NROWS (BB * TT)   // 524288 GEMM rows
#define MT32 (NROWS / 32) // 16384 m32 tiles
#define NCTA_P 288        // proj CTAs (2 per SM, 3 N-groups x 96)
#define WSTRIDE_P (96 * 8)// m32-tile warp stride per N-group

// Scratch: xproj[b*T + t][200] = x[b,t,:] @ kernel (fp32)
__device__ float g_xproj[(size_t)NROWS * GG];

// ---------------------------------------------------------------------------
// helpers
// ---------------------------------------------------------------------------
__device__ __forceinline__ uint32_t smem_u32(const void* p) {
    uint32_t a;
    asm("{ .reg .u64 t; cvta.to.shared.u64 t, %1; cvt.u32.u64 %0, t; }" : "=r"(a) : "l"(p));
    return a;
}

__device__ __forceinline__ uint32_t bf2pack(float a, float b) {
    __nv_bfloat162 t = __floats2bfloat162_rn(a, b);
    return *reinterpret_cast<uint32_t*>(&t);
}

// pack top 16 bits of two floats into bf16x2 (truncation split, 1 instr)
__device__ __forceinline__ uint32_t hipack(float a, float b) {
    uint32_t d;
    asm("prmt.b32 %0, %1, %2, 0x7632;" : "=r"(d)
        : "r"(__float_as_uint(a)), "r"(__float_as_uint(b)));
    return d;
}
__device__ __forceinline__ float trunc_hi(float v) {
    return __uint_as_float(__float_as_uint(v) & 0xffff0000u);
}

__device__ __forceinline__ void mma16816(float* d, uint32_t a0, uint32_t a1,
                                         uint32_t a2, uint32_t a3,
                                         uint32_t b0, uint32_t b1) {
    asm volatile(
        "mma.sync.aligned.m16n8k16.row.col.f32.bf16.bf16.f32 "
        "{%0,%1,%2,%3}, {%4,%5,%6,%7}, {%8,%9}, {%0,%1,%2,%3};"
        : "+f"(d[0]), "+f"(d[1]), "+f"(d[2]), "+f"(d[3])
        : "r"(a0), "r"(a1), "r"(a2), "r"(a3), "r"(b0), "r"(b1));
}

__device__ __forceinline__ void ldsm_x4(uint32_t& r0, uint32_t& r1,
                                        uint32_t& r2, uint32_t& r3, uint32_t addr) {
    asm volatile("ldmatrix.sync.aligned.m8n8.x4.shared.b16 {%0,%1,%2,%3}, [%4];"
                 : "=r"(r0), "=r"(r1), "=r"(r2), "=r"(r3) : "r"(addr));
}

// packed fp32x2 ops
__device__ __forceinline__ void fma2(uint64_t& d, uint64_t a, uint64_t b) {
    asm("fma.rn.f32x2 %0, %1, %2, %0;" : "+l"(d) : "l"(a), "l"(b));
}
__device__ __forceinline__ void add2(uint64_t& d, uint64_t a) {
    asm("add.rn.f32x2 %0, %0, %1;" : "+l"(d) : "l"(a));
}
__device__ __forceinline__ uint64_t pk2(float lo, float hi) {
    uint64_t r;
    asm("mov.b64 %0, {%1, %2};" : "=l"(r) : "f"(lo), "f"(hi));
    return r;
}
__device__ __forceinline__ void up2(float& lo, float& hi, uint64_t v) {
    asm("mov.b64 {%0, %1}, %2;" : "=f"(lo), "=f"(hi) : "l"(v));
}

__device__ __forceinline__ float fast_tanh(float v) {
    float y;
    asm("tanh.approx.f32 %0, %1;" : "=f"(y) : "f"(v));
    return y;
}
__device__ __forceinline__ float fast_sig(float v) {
    return fmaf(fast_tanh(0.5f * v), 0.5f, 0.5f);
}

// ---------------------------------------------------------------------------
// Kernel 1: projection GEMM xproj = x @ W via HMMA bf16, 3-term hi/lo split.
//   288 CTAs x 256 threads; 3 N-groups; each warp owns an m32 tile with
//   B-fragment reuse across the two m16 halves. [R9-measured: 278.8us]
// ---------------------------------------------------------------------------
#define NT 9                         // n-tiles per CTA group
#define NBROWS (NT * 8)              // 72 B rows staged
#define KP 136                       // padded B row stride in bf16
#define BROW (KP * 2)                // 272 bytes
#define SMB_LO (NBROWS * BROW)       // 19584
#define SMB_TOTAL (2 * NBROWS * BROW)// 39168 bytes

__global__ __launch_bounds__(256, 2)
void proj_kernel(const float* __restrict__ x, const float* __restrict__ W) {
    extern __shared__ char smem[];
    const uint32_t sb = smem_u32(smem);
    const int tid = threadIdx.x;
    const int wid = tid >> 5;
    const int lane = tid & 31;
    const int grpN = blockIdx.x % 3;
    const int noff = grpN * 64;       // global n float-offset of this slice

    for (int idx = tid; idx < NBROWS * FF; idx += 256) {
        int nl = idx >> 7;
        int k = idx & 127;
        float v = W[k * GG + (noff + nl)];
        __nv_bfloat16 hi = __float2bfloat16_rn(v);
        float lo = v - __bfloat162float(hi);
        uint32_t off = (uint32_t)(nl * BROW + k * 2);
        *reinterpret_cast<__nv_bfloat16*>(smem + off) = hi;
        *reinterpret_cast<__nv_bfloat16*>(smem + SMB_LO + off) = __float2bfloat16_rn(lo);
    }
    __syncthreads();

    const int l8 = lane & 7;
    const int grp = lane >> 3;
    const uint32_t lmOff = (uint32_t)(l8 * BROW + (grp & 1) * 16 + (grp >> 1) * SMB_LO);

    const int r = lane >> 2;
    const int cq = lane & 3;

    for (int mt = (blockIdx.x / 3) * 8 + wid; mt < MT32; mt += WSTRIDE_P) {
        const size_t row0 = (size_t)mt * 32 + r;

        const float* __restrict__ p0 = x + row0 * FF;
        const float* __restrict__ p1 = x + (row0 + 8) * FF;
        const float* __restrict__ p2 = x + (row0 + 16) * FF;
        const float* __restrict__ p3 = x + (row0 + 24) * FF;

        float acc0[NT][4], acc1[NT][4];
#pragma unroll
        for (int j = 0; j < NT; ++j) {
#pragma unroll
            for (int q = 0; q < 4; ++q) { acc0[j][q] = 0.f; acc1[j][q] = 0.f; }
        }

#pragma unroll
        for (int kk = 0; kk < 8; ++kk) {
            const int k0 = kk * 16;
            float2 f0 = *(const float2*)(p0 + k0 + 2 * cq);
            float2 f1 = *(const float2*)(p1 + k0 + 2 * cq);
            float2 f2 = *(const float2*)(p0 + k0 + 2 * cq + 8);
            float2 f3 = *(const float2*)(p1 + k0 + 2 * cq + 8);
            float2 g0 = *(const float2*)(p2 + k0 + 2 * cq);
            float2 g1 = *(const float2*)(p3 + k0 + 2 * cq);
            float2 g2 = *(const float2*)(p2 + k0 + 2 * cq + 8);
            float2 g3 = *(const float2*)(p3 + k0 + 2 * cq + 8);

            uint32_t ah0 = hipack(f0.x, f0.y), ah1 = hipack(f1.x, f1.y);
            uint32_t ah2 = hipack(f2.x, f2.y), ah3 = hipack(f3.x, f3.y);
            uint32_t al0 = bf2pack(f0.x - trunc_hi(f0.x), f0.y - trunc_hi(f0.y));
            uint32_t al1 = bf2pack(f1.x - trunc_hi(f1.x), f1.y - trunc_hi(f1.y));
            uint32_t al2 = bf2pack(f2.x - trunc_hi(f2.x), f2.y - trunc_hi(f2.y));
            uint32_t al3 = bf2pack(f3.x - trunc_hi(f3.x), f3.y - trunc_hi(f3.y));

            uint32_t bh0_ = hipack(g0.x, g0.y), bh1_ = hipack(g1.x, g1.y);
            uint32_t bh2_ = hipack(g2.x, g2.y), bh3_ = hipack(g3.x, g3.y);
            uint32_t bl0_ = bf2pack(g0.x - trunc_hi(g0.x), g0.y - trunc_hi(g0.y));
            uint32_t bl1_ = bf2pack(g1.x - trunc_hi(g1.x), g1.y - trunc_hi(g1.y));
            uint32_t bl2_ = bf2pack(g2.x - trunc_hi(g2.x), g2.y - trunc_hi(g2.y));
            uint32_t bl3_ = bf2pack(g3.x - trunc_hi(g3.x), g3.y - trunc_hi(g3.y));

            const uint32_t kOff = sb + (uint32_t)(k0 * 2) + lmOff;
#pragma unroll
            for (int j = 0; j < NT; ++j) {
                uint32_t wh0, wh1, wl0, wl1;
                ldsm_x4(wh0, wh1, wl0, wl1, kOff + (uint32_t)(j * 8 * BROW));
                mma16816(acc0[j], ah0, ah1, ah2, ah3, wh0, wh1);
                mma16816(acc0[j], ah0, ah1, ah2, ah3, wl0, wl1);
                mma16816(acc0[j], al0, al1, al2, al3, wh0, wh1);
                mma16816(acc1[j], bh0_, bh1_, bh2_, bh3_, wh0, wh1);
                mma16816(acc1[j], bh0_, bh1_, bh2_, bh3_, wl0, wl1);
                mma16816(acc1[j], bl0_, bl1_, bl2_, bl3_, wh0, wh1);
            }
        }

        float* __restrict__ d0 = g_xproj + row0 * GG + noff + 2 * cq;
        float* __restrict__ d1 = d0 + 8 * GG;
        float* __restrict__ d2 = d0 + 16 * GG;
        float* __restrict__ d3 = d0 + 24 * GG;
#pragma unroll
        for (int j = 0; j < NT; ++j) {
            *(float2*)(d0 + j * 8) = make_float2(acc0[j][0], acc0[j][1]);
            *(float2*)(d1 + j * 8) = make_float2(acc0[j][2], acc0[j][3]);
            *(float2*)(d2 + j * 8) = make_float2(acc1[j][0], acc1[j][1]);
            *(float2*)(d3 + j * 8) = make_float2(acc1[j][2], acc1[j][3]);
        }
    }
}

// ---------------------------------------------------------------------------
// Kernel 2: LSTM recurrence, f32x2 DUAL-ROW: batch rows (A,B) packed
//   element-wise into the two f32x2 lanes. One fma2 advances both rows for
//   one k. 256 CTAs x 224 threads (2 CTAs/SM). Thread tid<200 owns gate
//   column (tid&3)*50 + (tid>>2) so z_s[tid] stores are conflict-free and
//   the update phase reads one float4 (i,f,g~,o) per row per unit.
//   2 barriers per 2-row step = 1 barrier/row. R8-style specialized update.
// ---------------------------------------------------------------------------
__global__ __launch_bounds__(224, 2)
void lstm_kernel(const float* __restrict__ R, const float* __restrict__ bias,
                 const float* __restrict__ dw, const float* __restrict__ db,
                 float* __restrict__ out) {
    __shared__ __align__(16) float h_s[104];    // pairs (hA[k],hB[k]), k<52
    __shared__ __align__(16) float zA_s[224];   // z of row A, indexed by tid
    __shared__ __align__(16) float zB_s[224];

    const int tid = threadIdx.x;
    const int b0 = blockIdx.x * 2;
    const int g = tid & 3;            // gate: 0=i 1=f 2=g~ 3=o
    const int u = tid >> 2;           // unit
    int col = g * 50 + u;
    if (col > 199) col = 199;         // threads 200..223: harmless clamp

    uint64_t rw[UU];                  // duplicated weights (w_k, w_k)
#pragma unroll
    for (int k = 0; k < UU; ++k) {
        float w = R[k * GG + col];
        rw[k] = pk2(w, w);
    }
    const float bv = bias[col];

    for (int i = tid; i < 104; i += 224) h_s[i] = 0.f;
    float cA = 0.f, cB = 0.f;
    __syncthreads();

    const float* __restrict__ xpA = g_xproj + (size_t)b0 * TT * GG;
    const float* __restrict__ xpB = xpA + (size_t)TT * GG;
    float xvA = __ldcs(xpA + col);
    float xvB = __ldcs(xpB + col);

#pragma unroll 1
    for (int t = 0; t < TT; ++t) {
        int tn = (t + 1 < TT) ? (t + 1) : (TT - 1);
        float xnA = __ldcs(xpA + (size_t)tn * GG + col);
        float xnB = __ldcs(xpB + (size_t)tn * GG + col);

        // dual-row dot: 50 fma2 over pairs (hA[k],hB[k]), 4 chains
        uint64_t z2 = pk2(0.f, 0.f);
        uint64_t a0 = z2, a1 = z2, a2 = z2, a3 = z2;
#pragma unroll
        for (int i = 0; i < 12; ++i) {
            ulonglong2 h01 = *(const ulonglong2*)(h_s + 8 * i);      // pairs 4i,4i+1
            ulonglong2 h23 = *(const ulonglong2*)(h_s + 8 * i + 4);  // pairs 4i+2,4i+3
            fma2(a0, rw[4 * i + 0], h01.x);
            fma2(a1, rw[4 * i + 1], h01.y);
            fma2(a2, rw[4 * i + 2], h23.x);
            fma2(a3, rw[4 * i + 3], h23.y);
        }
        {
            ulonglong2 ht = *(const ulonglong2*)(h_s + 96);          // pairs 48,49
            fma2(a0, rw[48], ht.x);
            fma2(a1, rw[49], ht.y);
        }
        add2(a0, a1); add2(a2, a3); add2(a0, a2);
        float sA, sB;
        up2(sA, sB, a0);
        sA += bv + xvA;
        sB += bv + xvB;

        if (g == 2) { zA_s[tid] = fast_tanh(sA); zB_s[tid] = fast_tanh(sB); }
        else        { zA_s[tid] = fast_sig(sA);  zB_s[tid] = fast_sig(sB); }
        __syncthreads();

        if (tid < UU) {
            float4 za = *(const float4*)(zA_s + 4 * tid);  // i,f,g~,o
            float4 zb = *(const float4*)(zB_s + 4 * tid);
            cA = fmaf(za.y, cA, za.x * za.z);
            cB = fmaf(zb.y, cB, zb.x * zb.z);
            float hA = za.w * fast_tanh(cA);
            float hB = zb.w * fast_tanh(cB);
            *(float2*)(h_s + 2 * tid) = make_float2(hA, hB);
        }
        __syncthreads();
        xvA = xnA; xvB = xnB;
    }

    // dense head
    if (tid == 0) {
        float s = db[0];
#pragma unroll
        for (int k = 0; k < UU; ++k) s += h_s[2 * k] * dw[k];
        out[b0] = s;
    } else if (tid == 32) {
        float s = db[0];
#pragma unroll
        for (int k = 0; k < UU; ++k) s += h_s[2 * k + 1] * dw[k];
        out[b0 + 1] = s;
    }
}

// ---------------------------------------------------------------------------
extern "C" void kernel_launch(void* const* d_in, const int* in_sizes, int n_in,
                              void* d_out, int out_size) {
    const float* x    = (const float*)d_in[0];  // [512,1024,128]
    const float* W    = (const float*)d_in[1];  // [128,200]
    const float* R    = (const float*)d_in[2];  // [50,200]
    const float* bias = (const float*)d_in[3];  // [200]
    const float* dw   = (const float*)d_in[4];  // [50]
    const float* db   = (const float*)d_in[5];  // [1]
    float* out = (float*)d_out;                 // [512]
    (void)in_sizes; (void)n_in; (void)out_size;

    cudaFuncSetAttribute(proj_kernel,
                         cudaFuncAttributeMaxDynamicSharedMemorySize, SMB_TOTAL);

    // Launch period = 2: sampled launch index 3 -> lstm gets profiled.
    proj_kernel<<<NCTA_P, 256, SMB_TOTAL>>>(x, W);
    lstm_kernel<<<BB / 2, 224>>>(R, bias, dw, db, out);
}